// round 1
// baseline (speedup 1.0000x reference)
#include <cuda_runtime.h>
#include <math.h>

// ---------------- problem constants ----------------
#define D       128         // embedding dim
#define NMAX    6144        // max overlap size we support (actual ~2800)
#define LD      NMAX        // leading dim of sim^T scratch
#define KTOP    32
#define TAU_INV 10.0f
#define BITW    4096        // 4096 * 32 = 131072 bits >= U=100000
#define BT      64          // gemm tile
#define BK      32          // gemm k-chunk

// ---------------- device scratch (static, allowed) ----------------
__device__ float        g_Zw[(size_t)NMAX * D];
__device__ float        g_Zs[(size_t)NMAX * D];
__device__ float        g_G[(size_t)NMAX * NMAX];   // G[j*LD+i] = sim[i][j] (sim^T), /tau applied
__device__ float        g_rowloss[NMAX];
__device__ float        g_pair[3];
__device__ unsigned int g_bitmap[BITW];
__device__ int          g_common[NMAX];
__device__ int          g_N;
__device__ int          g_is64;

// ---------------- dtype detection (int64 vs int32 users) ----------------
// If users are int64 (LE) with values < 2^31, every odd int32 word of the
// buffer is 0. If int32, odd words are real user ids (P(all 64 zero) ~ 0).
__global__ void k_detect(const int* __restrict__ u, int n) {
    __shared__ int nz;
    if (threadIdx.x == 0) nz = 0;
    __syncthreads();
    int limit = n < 128 ? n : 128;
    for (int i = 1 + 2 * (int)threadIdx.x; i < limit; i += 2 * (int)blockDim.x)
        if (u[i] != 0) atomicAdd(&nz, 1);
    __syncthreads();
    if (threadIdx.x == 0) g_is64 = (nz == 0) ? 1 : 0;
}

__device__ __forceinline__ int get_user(const void* p, int i) {
    return g_is64 ? (int)((const long long*)p)[i] : ((const int*)p)[i];
}

// ---------------- bitmap membership ----------------
__global__ void k_zero() {
    int t = blockIdx.x * blockDim.x + threadIdx.x;
    for (int i = t; i < BITW; i += gridDim.x * blockDim.x) g_bitmap[i] = 0u;
    if (t == 0) g_N = 0;
}

__global__ void k_build(const void* __restrict__ us, int ns) {
    int i = blockIdx.x * blockDim.x + threadIdx.x;
    if (i < ns) {
        unsigned v = (unsigned)get_user(us, i);
        if (v < BITW * 32u) atomicOr(&g_bitmap[v >> 5], 1u << (v & 31));
    }
}

// ---------------- stable compaction (single CTA, order+dup preserving) ----------------
__global__ void __launch_bounds__(1024) k_compact(const void* __restrict__ uw, int nw) {
    __shared__ int s[1024];
    __shared__ int base_s;
    int t = threadIdx.x;
    if (t == 0) base_s = 0;
    __syncthreads();
    for (int c = 0; c < nw; c += 1024) {
        int i = c + t;
        int flag = 0, v = 0;
        if (i < nw) {
            v = get_user(uw, i);
            unsigned uv = (unsigned)v;
            flag = (uv < BITW * 32u) && ((g_bitmap[uv >> 5] >> (uv & 31)) & 1u);
        }
        s[t] = flag;
        __syncthreads();
        // Hillis-Steele inclusive scan
        for (int off = 1; off < 1024; off <<= 1) {
            int x = (t >= off) ? s[t - off] : 0;
            __syncthreads();
            s[t] += x;
            __syncthreads();
        }
        int incl  = s[t];
        int total = s[1023];
        int pos   = base_s + incl - 1;
        if (flag && pos < NMAX) g_common[pos] = v;
        __syncthreads();
        if (t == 0) base_s += total;
        __syncthreads();
    }
    if (t == 0) g_N = base_s > NMAX ? NMAX : base_s;
}

// ---------------- gather + L2 normalize (warp per row) ----------------
__global__ void __launch_bounds__(256) k_gather(const float* __restrict__ ew,
                                                const float* __restrict__ es) {
    int N = g_N;
    int lane   = threadIdx.x & 31;
    int w      = (blockIdx.x * blockDim.x + threadIdx.x) >> 5;
    int nwarps = (gridDim.x * blockDim.x) >> 5;
    for (int r = w; r < N; r += nwarps) {
        int u = g_common[r];
        {
            float4 a = ((const float4*)(ew + (size_t)u * D))[lane];
            float ss = a.x * a.x + a.y * a.y + a.z * a.z + a.w * a.w;
            #pragma unroll
            for (int o = 16; o; o >>= 1) ss += __shfl_xor_sync(0xffffffffu, ss, o);
            float inv = 1.0f / fmaxf(sqrtf(ss), 1e-12f);
            float4 o4 = make_float4(a.x * inv, a.y * inv, a.z * inv, a.w * inv);
            ((float4*)(g_Zw + (size_t)r * D))[lane] = o4;
        }
        {
            float4 b = ((const float4*)(es + (size_t)u * D))[lane];
            float ss = b.x * b.x + b.y * b.y + b.z * b.z + b.w * b.w;
            #pragma unroll
            for (int o = 16; o; o >>= 1) ss += __shfl_xor_sync(0xffffffffu, ss, o);
            float inv = 1.0f / fmaxf(sqrtf(ss), 1e-12f);
            float4 o4 = make_float4(b.x * inv, b.y * inv, b.z * inv, b.w * inv);
            ((float4*)(g_Zs + (size_t)r * D))[lane] = o4;
        }
    }
}

// ---------------- persistent tiled GEMM: G[j*LD+i] = dot(Zw[j], Zs[i]) / tau -------
__global__ void __launch_bounds__(256) k_gemm() {
    __shared__ float As[BK][BT + 4];   // Zw chunk, k-major
    __shared__ float Bs[BK][BT + 4];   // Zs chunk, k-major
    int N = g_N;
    if (N <= 0) return;
    int nb = (N + BT - 1) / BT;
    long ntiles = (long)nb * nb;
    int tid = threadIdx.x;
    int tx = tid & 15;   // -> i (contiguous store dim)
    int ty = tid >> 4;   // -> j
    for (long t = blockIdx.x; t < ntiles; t += gridDim.x) {
        int jb = (int)(t / nb), ib = (int)(t % nb);
        int j0 = jb * BT, i0 = ib * BT;
        float c[4][4];
        #pragma unroll
        for (int a = 0; a < 4; a++)
            #pragma unroll
            for (int b = 0; b < 4; b++) c[a][b] = 0.0f;

        for (int k0 = 0; k0 < D; k0 += BK) {
            __syncthreads();
            #pragma unroll
            for (int q = tid; q < 512; q += 256) {
                int row = q >> 3;   // 0..63
                int c4  = q & 7;    // 0..7 (x4 floats)
                float4 a = (j0 + row < N)
                    ? ((const float4*)(g_Zw + (size_t)(j0 + row) * D + k0))[c4]
                    : make_float4(0.f, 0.f, 0.f, 0.f);
                As[c4 * 4 + 0][row] = a.x;
                As[c4 * 4 + 1][row] = a.y;
                As[c4 * 4 + 2][row] = a.z;
                As[c4 * 4 + 3][row] = a.w;
                float4 b = (i0 + row < N)
                    ? ((const float4*)(g_Zs + (size_t)(i0 + row) * D + k0))[c4]
                    : make_float4(0.f, 0.f, 0.f, 0.f);
                Bs[c4 * 4 + 0][row] = b.x;
                Bs[c4 * 4 + 1][row] = b.y;
                Bs[c4 * 4 + 2][row] = b.z;
                Bs[c4 * 4 + 3][row] = b.w;
            }
            __syncthreads();
            #pragma unroll
            for (int k = 0; k < BK; k++) {
                float4 av = *(const float4*)&As[k][ty * 4];
                float4 bv = *(const float4*)&Bs[k][tx * 4];
                float aj[4] = {av.x, av.y, av.z, av.w};
                float bi[4] = {bv.x, bv.y, bv.z, bv.w};
                #pragma unroll
                for (int jj = 0; jj < 4; jj++)
                    #pragma unroll
                    for (int ii = 0; ii < 4; ii++)
                        c[jj][ii] += aj[jj] * bi[ii];
            }
        }
        #pragma unroll
        for (int jj = 0; jj < 4; jj++) {
            int j = j0 + ty * 4 + jj;
            if (j < N) {
                #pragma unroll
                for (int ii = 0; ii < 4; ii++) {
                    int i = i0 + tx * 4 + ii;
                    if (i < N) g_G[(size_t)j * LD + i] = c[jj][ii] * TAU_INV;
                }
            }
        }
    }
}

// ---------------- per-row streaming top-32 + logsumexp ----------------
__global__ void __launch_bounds__(256) k_topk() {
    int N = g_N;
    int i = blockIdx.x * blockDim.x + threadIdx.x;
    if (i >= N) return;
    float T[KTOP];
    #pragma unroll
    for (int k = 0; k < KTOP; k++) T[k] = -INFINITY;
    float tmin = -INFINITY;
    int   minidx = 0;
    float pos = 0.0f;

    int j = 0;
    for (; j + 4 <= N; j += 4) {
        float v0 = g_G[(size_t)(j + 0) * LD + i];
        float v1 = g_G[(size_t)(j + 1) * LD + i];
        float v2 = g_G[(size_t)(j + 2) * LD + i];
        float v3 = g_G[(size_t)(j + 3) * LD + i];
        float vv[4] = {v0, v1, v2, v3};
        #pragma unroll
        for (int u = 0; u < 4; u++) {
            int jj = j + u;
            float v = vv[u];
            if (jj == i) { pos = v; continue; }
            if (v > tmin) {
                T[minidx] = v;
                tmin = T[0]; minidx = 0;
                #pragma unroll
                for (int k = 1; k < KTOP; k++)
                    if (T[k] < tmin) { tmin = T[k]; minidx = k; }
            }
        }
    }
    for (; j < N; j++) {
        float v = g_G[(size_t)j * LD + i];
        if (j == i) { pos = v; continue; }
        if (v > tmin) {
            T[minidx] = v;
            tmin = T[0]; minidx = 0;
            #pragma unroll
            for (int k = 1; k < KTOP; k++)
                if (T[k] < tmin) { tmin = T[k]; minidx = k; }
        }
    }

    float m = pos;
    #pragma unroll
    for (int k = 0; k < KTOP; k++) m = fmaxf(m, T[k]);
    float s = expf(pos - m);
    #pragma unroll
    for (int k = 0; k < KTOP; k++) s += expf(T[k] - m);   // expf(-inf)=0 pads short rows
    g_rowloss[i] = m + logf(s) - pos;
}

// ---------------- deterministic fixed-order reduction ----------------
__global__ void __launch_bounds__(1024) k_reduce(int p) {
    __shared__ float s[1024];
    int N = g_N;
    int t = threadIdx.x;
    float acc = 0.0f;
    for (int i = t; i < N; i += 1024) acc += g_rowloss[i];
    s[t] = acc;
    __syncthreads();
    for (int o = 512; o; o >>= 1) {
        if (t < o) s[t] += s[t + o];
        __syncthreads();
    }
    if (t == 0) g_pair[p] = (N >= 4) ? s[0] / (float)N : 0.0f;
}

__global__ void k_final(float* __restrict__ out) {
    out[0] = 0.2f * g_pair[0] + 1.0f * g_pair[1] + 1.0f * g_pair[2];
}

// ---------------- launch ----------------
extern "C" void kernel_launch(void* const* d_in, const int* in_sizes, int n_in,
                              void* d_out, int out_size) {
    const float* ev = (const float*)d_in[0];
    const float* ec = (const float*)d_in[1];
    const float* ep = (const float*)d_in[2];
    const void*  uv = d_in[3]; int nv = in_sizes[3];
    const void*  uc = d_in[4]; int nc = in_sizes[4];
    const void*  up = d_in[5]; int np_ = in_sizes[5];

    k_detect<<<1, 64>>>((const int*)uv, nv);

    struct PairCfg {
        const void* uw; int nw;
        const void* us; int ns;
        const float* ew; const float* es;
        int idx;
    };
    PairCfg pairs[3] = {
        { uv, nv, uc, nc,  ev, ec, 0 },   // (view, cart)     w=0.2
        { uc, nc, up, np_, ec, ep, 1 },   // (cart, purchase) w=1.0
        { uv, nv, up, np_, ev, ep, 2 },   // (view, purchase) w=1.0
    };

    for (int p = 0; p < 3; p++) {
        const PairCfg& P = pairs[p];
        k_zero<<<8, 512>>>();
        k_build<<<(P.ns + 255) / 256, 256>>>(P.us, P.ns);
        k_compact<<<1, 1024>>>(P.uw, P.nw);
        k_gather<<<296, 256>>>(P.ew, P.es);
        k_gemm<<<444, 256>>>();
        k_topk<<<(NMAX + 255) / 256, 256>>>();
        k_reduce<<<1, 1024>>>(P.idx);
    }
    k_final<<<1, 1>>>((float*)d_out);
}

// round 2
// speedup vs baseline: 6.2525x; 6.2525x over previous
#include <cuda_runtime.h>
#include <math.h>

// ---------------- problem constants ----------------
#define D        128
#define NMAX     4096          // max overlap (actual ~2800, 26-sigma margin)
#define LD       4096
#define KTOP     32
#define TAU_INV  10.0f
#define BITW     4096          // 4096*32 = 131072 bits >= U=100000
#define GT       128           // gemm tile
#define GK       16            // gemm k-chunk
#define NCHUNK   16            // top-k chunks per row

// ---------------- device scratch ----------------
__device__ float        g_Zw[3][(size_t)NMAX * D];
__device__ float        g_Zs[3][(size_t)NMAX * D];
__device__ float        g_G[3][(size_t)NMAX * NMAX];      // G[p][j*LD+i] = sim_p[i][j]*10
__device__ float        g_cand[3][(size_t)NMAX * NCHUNK * KTOP];
__device__ float        g_rowloss[3][NMAX];
__device__ float        g_pair[3];
__device__ unsigned int g_bitmap[2][BITW];                  // 0: cart set, 1: purchase set
__device__ int          g_common[3][NMAX];
__device__ int          g_N[3];
__device__ int          g_is64;

// ---------------- f32x2 helpers (FFMA2 pipe, PTX-only) ----------------
typedef unsigned long long ull;
__device__ __forceinline__ ull pack2(float x, float y) {
    ull r; asm("mov.b64 %0,{%1,%2};" : "=l"(r) : "f"(x), "f"(y)); return r;
}
__device__ __forceinline__ void ffma2(ull& c, ull a, ull b) {
    asm("fma.rn.f32x2 %0,%1,%2,%0;" : "+l"(c) : "l"(a), "l"(b));
}

// ---------------- int64 vs int32 detection ----------------
__global__ void k_detect(const int* __restrict__ u, int n) {
    __shared__ int nz;
    if (threadIdx.x == 0) nz = 0;
    __syncthreads();
    int limit = n < 128 ? n : 128;
    for (int i = 1 + 2 * (int)threadIdx.x; i < limit; i += 2 * (int)blockDim.x)
        if (u[i] != 0) atomicAdd(&nz, 1);
    __syncthreads();
    if (threadIdx.x == 0) g_is64 = (nz == 0) ? 1 : 0;
}
__device__ __forceinline__ int get_user(const void* p, int i) {
    return g_is64 ? (int)((const long long*)p)[i] : ((const int*)p)[i];
}

// ---------------- bitmaps ----------------
__global__ void k_zero() {
    int t = blockIdx.x * blockDim.x + threadIdx.x;
    for (int i = t; i < 2 * BITW; i += gridDim.x * blockDim.x)
        ((unsigned int*)g_bitmap)[i] = 0u;
    if (t < 3) g_N[t] = 0;
}
__global__ void k_build(const void* __restrict__ uc, int nc,
                        const void* __restrict__ up, int npv) {
    int i = blockIdx.x * blockDim.x + threadIdx.x;
    if (i < nc) {
        unsigned v = (unsigned)get_user(uc, i);
        if (v < BITW * 32u) atomicOr(&g_bitmap[0][v >> 5], 1u << (v & 31));
    }
    if (i < npv) {
        unsigned v = (unsigned)get_user(up, i);
        if (v < BITW * 32u) atomicOr(&g_bitmap[1][v >> 5], 1u << (v & 31));
    }
}

// ---------------- stable compaction: 3 CTAs, ballot scan ----------------
__global__ void __launch_bounds__(1024)
k_compact(const void* uw0, int n0, const void* uw1, int n1,
          const void* uw2, int n2) {
    int p = blockIdx.x;
    const void* uw = p == 0 ? uw0 : (p == 1 ? uw1 : uw2);
    int nw         = p == 0 ? n0  : (p == 1 ? n1  : n2);
    int bm         = p == 0 ? 0 : 1;    // pair0 strong=cart, pair1/2 strong=purchase

    __shared__ int wtot[32];
    __shared__ int woff[32];
    __shared__ int sbase, stot;
    int t = threadIdx.x, lane = t & 31, wid = t >> 5;
    if (t == 0) sbase = 0;
    __syncthreads();

    for (int c = 0; c < nw; c += 1024) {
        int i = c + t;
        int flag = 0, v = 0;
        if (i < nw) {
            v = get_user(uw, i);
            unsigned uv = (unsigned)v;
            flag = (uv < BITW * 32u) && ((g_bitmap[bm][uv >> 5] >> (uv & 31)) & 1u);
        }
        unsigned b = __ballot_sync(0xffffffffu, flag);
        int wp = __popc(b & ((1u << lane) - 1));
        if (lane == 0) wtot[wid] = __popc(b);
        __syncthreads();
        if (wid == 0) {
            int val = wtot[lane];
            int inc = val;
            #pragma unroll
            for (int o = 1; o < 32; o <<= 1) {
                int y = __shfl_up_sync(0xffffffffu, inc, o);
                if (lane >= o) inc += y;
            }
            woff[lane] = inc - val;
            if (lane == 31) stot = inc;
        }
        __syncthreads();
        int pos = sbase + woff[wid] + wp;
        if (flag && pos < NMAX) g_common[p][pos] = v;
        __syncthreads();
        if (t == 0) sbase += stot;
        __syncthreads();
    }
    if (t == 0) g_N[p] = sbase > NMAX ? NMAX : sbase;
}

// ---------------- gather + L2-normalize: warp/row, pair = blockIdx.y -----
__global__ void __launch_bounds__(256)
k_gather(const float* ev, const float* ec, const float* ep) {
    int p = blockIdx.y;
    const float* ew = p == 0 ? ev : (p == 1 ? ec : ev);
    const float* es = p == 0 ? ec : ep;
    int N = g_N[p];
    int lane = threadIdx.x & 31;
    int row  = blockIdx.x * 8 + (threadIdx.x >> 5);
    if (row >= N) return;
    int u = g_common[p][row];
    {
        float4 a = ((const float4*)(ew + (size_t)u * D))[lane];
        float ss = a.x * a.x + a.y * a.y + a.z * a.z + a.w * a.w;
        #pragma unroll
        for (int o = 16; o; o >>= 1) ss += __shfl_xor_sync(0xffffffffu, ss, o);
        float inv = 1.0f / fmaxf(sqrtf(ss), 1e-12f);
        ((float4*)(g_Zw[p] + (size_t)row * D))[lane] =
            make_float4(a.x * inv, a.y * inv, a.z * inv, a.w * inv);
    }
    {
        float4 a = ((const float4*)(es + (size_t)u * D))[lane];
        float ss = a.x * a.x + a.y * a.y + a.z * a.z + a.w * a.w;
        #pragma unroll
        for (int o = 16; o; o >>= 1) ss += __shfl_xor_sync(0xffffffffu, ss, o);
        float inv = 1.0f / fmaxf(sqrtf(ss), 1e-12f);
        ((float4*)(g_Zs[p] + (size_t)row * D))[lane] =
            make_float4(a.x * inv, a.y * inv, a.z * inv, a.w * inv);
    }
}

// ---------------- persistent GEMM, 128x128 tile, 8x8 microtile, FFMA2 ----
// G[p][j*LD+i] = 10 * dot(Zw[p][j], Zs[p][i]).  Rows >= N are zero-padded
// (static zero-init, never written), so tiles need no bounds checks.
__global__ void __launch_bounds__(256) k_gemm() {
    __shared__ __align__(16) float As[GK][GT + 4];
    __shared__ __align__(16) float Bs[GK][GT + 4];

    int nb0 = (g_N[0] + GT - 1) >> 7, nt0 = nb0 * nb0;
    int nb1 = (g_N[1] + GT - 1) >> 7, nt1 = nb1 * nb1;
    int nb2 = (g_N[2] + GT - 1) >> 7, nt2 = nb2 * nb2;
    int total = nt0 + nt1 + nt2;

    int tid = threadIdx.x;
    int tx = tid & 15;     // -> i (8 cols each)
    int ty = tid >> 4;     // -> j (8 rows each)

    for (int t = blockIdx.x; t < total; t += gridDim.x) {
        int p, tt, nb;
        if (t < nt0)            { p = 0; tt = t;             nb = nb0; }
        else if (t < nt0 + nt1) { p = 1; tt = t - nt0;       nb = nb1; }
        else                    { p = 2; tt = t - nt0 - nt1; nb = nb2; }
        const float* Zw = g_Zw[p];
        const float* Zs = g_Zs[p];
        float*       G  = g_G[p];
        int j0 = (tt / nb) << 7;
        int i0 = (tt % nb) << 7;

        ull c[8][4];
        #pragma unroll
        for (int a = 0; a < 8; a++)
            #pragma unroll
            for (int b = 0; b < 4; b++) c[a][b] = 0ull;

        for (int k0 = 0; k0 < D; k0 += GK) {
            __syncthreads();
            #pragma unroll
            for (int q = tid; q < 512; q += 256) {
                int row = q >> 2, c4 = q & 3;
                float4 a = ((const float4*)(Zw + (size_t)(j0 + row) * D + k0))[c4];
                As[c4 * 4 + 0][row] = a.x; As[c4 * 4 + 1][row] = a.y;
                As[c4 * 4 + 2][row] = a.z; As[c4 * 4 + 3][row] = a.w;
                float4 b = ((const float4*)(Zs + (size_t)(i0 + row) * D + k0))[c4];
                Bs[c4 * 4 + 0][row] = b.x; Bs[c4 * 4 + 1][row] = b.y;
                Bs[c4 * 4 + 2][row] = b.z; Bs[c4 * 4 + 3][row] = b.w;
            }
            __syncthreads();
            #pragma unroll
            for (int k = 0; k < GK; k++) {
                float4 a0 = *(const float4*)&As[k][ty * 8];
                float4 a1 = *(const float4*)&As[k][ty * 8 + 4];
                float4 b0 = *(const float4*)&Bs[k][tx * 8];
                float4 b1 = *(const float4*)&Bs[k][tx * 8 + 4];
                ull B[4] = { pack2(b0.x, b0.y), pack2(b0.z, b0.w),
                             pack2(b1.x, b1.y), pack2(b1.z, b1.w) };
                float av[8] = { a0.x, a0.y, a0.z, a0.w, a1.x, a1.y, a1.z, a1.w };
                #pragma unroll
                for (int jj = 0; jj < 8; jj++) {
                    ull aa = pack2(av[jj], av[jj]);
                    #pragma unroll
                    for (int ii = 0; ii < 4; ii++) ffma2(c[jj][ii], aa, B[ii]);
                }
            }
        }
        #pragma unroll
        for (int jj = 0; jj < 8; jj++) {
            float2* rowp = (float2*)(G + (size_t)(j0 + ty * 8 + jj) * LD + i0 + tx * 8);
            #pragma unroll
            for (int ii = 0; ii < 4; ii++) {
                float2 v = *(float2*)&c[jj][ii];
                v.x *= TAU_INV; v.y *= TAU_INV;
                rowp[ii] = v;
            }
        }
    }
}

// ---------------- sorted-descending register top-32 insert ----------------
// One pass of max/min: inserts v into sorted T, drops the old minimum.
#define TK_INSERT(T, v)                                   \
    do { float _v = (v);                                  \
        _Pragma("unroll")                                 \
        for (int _k = 0; _k < KTOP; _k++) {               \
            float _t = T[_k];                             \
            T[_k] = fmaxf(_t, _v);                        \
            _v = fminf(_t, _v);                           \
        }                                                 \
    } while (0)

// ---------------- chunked per-row top-32 pass 1 ----------------
__global__ void __launch_bounds__(256) k_topk_chunk() {
    int p = blockIdx.z;
    int c = blockIdx.y;
    int i = blockIdx.x * 256 + threadIdx.x;
    int N = g_N[p];
    if (i >= N) return;

    const float* G = g_G[p];
    int len = (N + NCHUNK - 1) / NCHUNK;
    int j0 = c * len;
    int j1 = j0 + len; if (j1 > N) j1 = N;

    float T[KTOP];
    #pragma unroll
    for (int k = 0; k < KTOP; k++) T[k] = -INFINITY;

    int j = j0;
    for (; j + 4 <= j1; j += 4) {
        float v0 = G[(size_t)(j + 0) * LD + i];
        float v1 = G[(size_t)(j + 1) * LD + i];
        float v2 = G[(size_t)(j + 2) * LD + i];
        float v3 = G[(size_t)(j + 3) * LD + i];
        if (j + 0 != i && v0 > T[KTOP - 1]) TK_INSERT(T, v0);
        if (j + 1 != i && v1 > T[KTOP - 1]) TK_INSERT(T, v1);
        if (j + 2 != i && v2 > T[KTOP - 1]) TK_INSERT(T, v2);
        if (j + 3 != i && v3 > T[KTOP - 1]) TK_INSERT(T, v3);
    }
    for (; j < j1; j++) {
        float v = G[(size_t)j * LD + i];
        if (j != i && v > T[KTOP - 1]) TK_INSERT(T, v);
    }

    float* cand = g_cand[p] + ((size_t)i * NCHUNK + c) * KTOP;
    #pragma unroll
    for (int k = 0; k < KTOP; k++) cand[k] = T[k];
}

// ---------------- merge candidates + logsumexp ----------------
__global__ void __launch_bounds__(256) k_merge() {
    int p = blockIdx.z;
    int i = blockIdx.x * 256 + threadIdx.x;
    int N = g_N[p];
    if (i >= N) return;

    const float4* cand = (const float4*)(g_cand[p] + (size_t)i * NCHUNK * KTOP);
    float T[KTOP];
    #pragma unroll
    for (int k = 0; k < KTOP; k++) T[k] = -INFINITY;

    #pragma unroll 4
    for (int q = 0; q < NCHUNK * KTOP / 4; q++) {
        float4 v = cand[q];
        if (v.x > T[KTOP - 1]) TK_INSERT(T, v.x);
        if (v.y > T[KTOP - 1]) TK_INSERT(T, v.y);
        if (v.z > T[KTOP - 1]) TK_INSERT(T, v.z);
        if (v.w > T[KTOP - 1]) TK_INSERT(T, v.w);
    }

    float pos = g_G[p][(size_t)i * LD + i];
    float m = fmaxf(pos, T[0]);               // T[0] is the max (sorted desc)
    float s = expf(pos - m);
    #pragma unroll
    for (int k = 0; k < KTOP; k++) s += expf(T[k] - m);   // exp(-inf)=0 pads
    g_rowloss[p][i] = m + logf(s) - pos;
}

// ---------------- deterministic reduction ----------------
__global__ void __launch_bounds__(1024) k_reduce() {
    __shared__ float s[1024];
    int p = blockIdx.x;
    int N = g_N[p];
    int t = threadIdx.x;
    float acc = 0.0f;
    for (int i = t; i < N; i += 1024) acc += g_rowloss[p][i];
    s[t] = acc;
    __syncthreads();
    for (int o = 512; o; o >>= 1) {
        if (t < o) s[t] += s[t + o];
        __syncthreads();
    }
    if (t == 0) g_pair[p] = (N >= 4) ? s[0] / (float)N : 0.0f;
}

__global__ void k_final(float* __restrict__ out) {
    out[0] = 0.2f * g_pair[0] + 1.0f * g_pair[1] + 1.0f * g_pair[2];
}

// ---------------- launch ----------------
extern "C" void kernel_launch(void* const* d_in, const int* in_sizes, int n_in,
                              void* d_out, int out_size) {
    const float* ev = (const float*)d_in[0];
    const float* ec = (const float*)d_in[1];
    const float* ep = (const float*)d_in[2];
    const void*  uv = d_in[3]; int nv  = in_sizes[3];
    const void*  uc = d_in[4]; int nc  = in_sizes[4];
    const void*  up = d_in[5]; int np_ = in_sizes[5];

    k_detect<<<1, 64>>>((const int*)uv, nv);
    k_zero<<<8, 512>>>();
    int nmaxb = (nv > nc ? nv : nc);
    if (np_ > nmaxb) nmaxb = np_;
    k_build<<<(nmaxb + 255) / 256, 256>>>(uc, nc, up, np_);
    // pairs: (view->cart), (cart->purchase), (view->purchase)
    k_compact<<<3, 1024>>>(uv, nv, uc, nc, uv, nv);
    k_gather<<<dim3(NMAX / 8, 3), 256>>>(ev, ec, ep);
    k_gemm<<<296, 256>>>();
    k_topk_chunk<<<dim3(NMAX / 256, NCHUNK, 3), 256>>>();
    k_merge<<<dim3(NMAX / 256, 1, 3), 256>>>();
    k_reduce<<<3, 1024>>>();
    k_final<<<1, 1>>>((float*)d_out);
}

// round 3
// speedup vs baseline: 6.2632x; 1.0017x over previous
#include <cuda_runtime.h>
#include <math.h>

// ---------------- problem constants ----------------
#define D        128
#define NMAX     4096          // max overlap (actual ~2800, 26-sigma margin)
#define LD       4096
#define KTOP     32
#define TAU_INV  10.0f
#define BITW     4096          // 4096*32 = 131072 bits >= U=100000
#define GT       128           // gemm tile
#define GK       16            // gemm k-chunk
#define NCHUNK   16            // top-k chunks per row

// ---------------- device scratch ----------------
__device__ float        g_Zw[3][(size_t)NMAX * D];
__device__ float        g_Zs[3][(size_t)NMAX * D];
__device__ float        g_G[3][(size_t)NMAX * NMAX];      // G[p][j*LD+i] = sim_p[i][j]*10
__device__ float        g_cand[3][(size_t)NMAX * NCHUNK * KTOP];
__device__ float        g_rowloss[3][NMAX];
__device__ float        g_pair[3];
__device__ unsigned int g_bitmap[2][BITW];                  // 0: cart set, 1: purchase set
__device__ int          g_common[3][NMAX];
__device__ int          g_N[3];
__device__ int          g_is64;

// ---------------- f32x2 helpers (FFMA2 pipe, PTX-only) ----------------
typedef unsigned long long ull;
__device__ __forceinline__ ull pack2(float x, float y) {
    ull r; asm("mov.b64 %0,{%1,%2};" : "=l"(r) : "f"(x), "f"(y)); return r;
}
__device__ __forceinline__ void ffma2(ull& c, ull a, ull b) {
    asm("fma.rn.f32x2 %0,%1,%2,%0;" : "+l"(c) : "l"(a), "l"(b));
}

// ---------------- int64 vs int32 detection ----------------
__global__ void k_detect(const int* __restrict__ u, int n) {
    __shared__ int nz;
    if (threadIdx.x == 0) nz = 0;
    __syncthreads();
    int limit = n < 128 ? n : 128;
    for (int i = 1 + 2 * (int)threadIdx.x; i < limit; i += 2 * (int)blockDim.x)
        if (u[i] != 0) atomicAdd(&nz, 1);
    __syncthreads();
    if (threadIdx.x == 0) g_is64 = (nz == 0) ? 1 : 0;
}
__device__ __forceinline__ int get_user(const void* p, int i) {
    return g_is64 ? (int)((const long long*)p)[i] : ((const int*)p)[i];
}

// ---------------- bitmaps ----------------
__global__ void k_zero() {
    int t = blockIdx.x * blockDim.x + threadIdx.x;
    for (int i = t; i < 2 * BITW; i += gridDim.x * blockDim.x)
        ((unsigned int*)g_bitmap)[i] = 0u;
    if (t < 3) g_N[t] = 0;
}
__global__ void k_build(const void* __restrict__ uc, int nc,
                        const void* __restrict__ up, int npv) {
    int i = blockIdx.x * blockDim.x + threadIdx.x;
    if (i < nc) {
        unsigned v = (unsigned)get_user(uc, i);
        if (v < BITW * 32u) atomicOr(&g_bitmap[0][v >> 5], 1u << (v & 31));
    }
    if (i < npv) {
        unsigned v = (unsigned)get_user(up, i);
        if (v < BITW * 32u) atomicOr(&g_bitmap[1][v >> 5], 1u << (v & 31));
    }
}

// ---------------- stable compaction: 3 CTAs, ballot scan ----------------
__global__ void __launch_bounds__(1024)
k_compact(const void* uw0, int n0, const void* uw1, int n1,
          const void* uw2, int n2) {
    int p = blockIdx.x;
    const void* uw = p == 0 ? uw0 : (p == 1 ? uw1 : uw2);
    int nw         = p == 0 ? n0  : (p == 1 ? n1  : n2);
    int bm         = p == 0 ? 0 : 1;    // pair0 strong=cart, pair1/2 strong=purchase

    __shared__ int wtot[32];
    __shared__ int woff[32];
    __shared__ int sbase, stot;
    int t = threadIdx.x, lane = t & 31, wid = t >> 5;
    if (t == 0) sbase = 0;
    __syncthreads();

    for (int c = 0; c < nw; c += 1024) {
        int i = c + t;
        int flag = 0, v = 0;
        if (i < nw) {
            v = get_user(uw, i);
            unsigned uv = (unsigned)v;
            flag = (uv < BITW * 32u) && ((g_bitmap[bm][uv >> 5] >> (uv & 31)) & 1u);
        }
        unsigned b = __ballot_sync(0xffffffffu, flag);
        int wp = __popc(b & ((1u << lane) - 1));
        if (lane == 0) wtot[wid] = __popc(b);
        __syncthreads();
        if (wid == 0) {
            int val = wtot[lane];
            int inc = val;
            #pragma unroll
            for (int o = 1; o < 32; o <<= 1) {
                int y = __shfl_up_sync(0xffffffffu, inc, o);
                if (lane >= o) inc += y;
            }
            woff[lane] = inc - val;
            if (lane == 31) stot = inc;
        }
        __syncthreads();
        int pos = sbase + woff[wid] + wp;
        if (flag && pos < NMAX) g_common[p][pos] = v;
        __syncthreads();
        if (t == 0) sbase += stot;
        __syncthreads();
    }
    if (t == 0) g_N[p] = sbase > NMAX ? NMAX : sbase;
}

// ---------------- gather + L2-normalize: warp/row, pair = blockIdx.y -----
__global__ void __launch_bounds__(256)
k_gather(const float* ev, const float* ec, const float* ep) {
    int p = blockIdx.y;
    const float* ew = p == 0 ? ev : (p == 1 ? ec : ev);
    const float* es = p == 0 ? ec : ep;
    int N = g_N[p];
    int lane = threadIdx.x & 31;
    int row  = blockIdx.x * 8 + (threadIdx.x >> 5);
    if (row >= N) return;
    int u = g_common[p][row];
    {
        float4 a = ((const float4*)(ew + (size_t)u * D))[lane];
        float ss = a.x * a.x + a.y * a.y + a.z * a.z + a.w * a.w;
        #pragma unroll
        for (int o = 16; o; o >>= 1) ss += __shfl_xor_sync(0xffffffffu, ss, o);
        float inv = 1.0f / fmaxf(sqrtf(ss), 1e-12f);
        ((float4*)(g_Zw[p] + (size_t)row * D))[lane] =
            make_float4(a.x * inv, a.y * inv, a.z * inv, a.w * inv);
    }
    {
        float4 a = ((const float4*)(es + (size_t)u * D))[lane];
        float ss = a.x * a.x + a.y * a.y + a.z * a.z + a.w * a.w;
        #pragma unroll
        for (int o = 16; o; o >>= 1) ss += __shfl_xor_sync(0xffffffffu, ss, o);
        float inv = 1.0f / fmaxf(sqrtf(ss), 1e-12f);
        ((float4*)(g_Zs[p] + (size_t)row * D))[lane] =
            make_float4(a.x * inv, a.y * inv, a.z * inv, a.w * inv);
    }
}

// ---------------- persistent GEMM, 128x128 tile, 8x8 microtile, FFMA2 ----
// G[p][j*LD+i] = 10 * dot(Zw[p][j], Zs[p][i]).  Rows >= N are zero-padded
// (static zero-init, never written), so tiles need no bounds checks.
__global__ void __launch_bounds__(256) k_gemm() {
    __shared__ __align__(16) float As[GK][GT + 4];
    __shared__ __align__(16) float Bs[GK][GT + 4];

    int nb0 = (g_N[0] + GT - 1) >> 7, nt0 = nb0 * nb0;
    int nb1 = (g_N[1] + GT - 1) >> 7, nt1 = nb1 * nb1;
    int nb2 = (g_N[2] + GT - 1) >> 7, nt2 = nb2 * nb2;
    int total = nt0 + nt1 + nt2;

    int tid = threadIdx.x;
    int tx = tid & 15;     // -> i (8 cols each)
    int ty = tid >> 4;     // -> j (8 rows each)

    for (int t = blockIdx.x; t < total; t += gridDim.x) {
        int p, tt, nb;
        if (t < nt0)            { p = 0; tt = t;             nb = nb0; }
        else if (t < nt0 + nt1) { p = 1; tt = t - nt0;       nb = nb1; }
        else                    { p = 2; tt = t - nt0 - nt1; nb = nb2; }
        const float* Zw = g_Zw[p];
        const float* Zs = g_Zs[p];
        float*       G  = g_G[p];
        int j0 = (tt / nb) << 7;
        int i0 = (tt % nb) << 7;

        ull c[8][4];
        #pragma unroll
        for (int a = 0; a < 8; a++)
            #pragma unroll
            for (int b = 0; b < 4; b++) c[a][b] = 0ull;

        for (int k0 = 0; k0 < D; k0 += GK) {
            __syncthreads();
            #pragma unroll
            for (int q = tid; q < 512; q += 256) {
                int row = q >> 2, c4 = q & 3;
                float4 a = ((const float4*)(Zw + (size_t)(j0 + row) * D + k0))[c4];
                As[c4 * 4 + 0][row] = a.x; As[c4 * 4 + 1][row] = a.y;
                As[c4 * 4 + 2][row] = a.z; As[c4 * 4 + 3][row] = a.w;
                float4 b = ((const float4*)(Zs + (size_t)(i0 + row) * D + k0))[c4];
                Bs[c4 * 4 + 0][row] = b.x; Bs[c4 * 4 + 1][row] = b.y;
                Bs[c4 * 4 + 2][row] = b.z; Bs[c4 * 4 + 3][row] = b.w;
            }
            __syncthreads();
            #pragma unroll
            for (int k = 0; k < GK; k++) {
                float4 a0 = *(const float4*)&As[k][ty * 8];
                float4 a1 = *(const float4*)&As[k][ty * 8 + 4];
                float4 b0 = *(const float4*)&Bs[k][tx * 8];
                float4 b1 = *(const float4*)&Bs[k][tx * 8 + 4];
                ull B[4] = { pack2(b0.x, b0.y), pack2(b0.z, b0.w),
                             pack2(b1.x, b1.y), pack2(b1.z, b1.w) };
                float av[8] = { a0.x, a0.y, a0.z, a0.w, a1.x, a1.y, a1.z, a1.w };
                #pragma unroll
                for (int jj = 0; jj < 8; jj++) {
                    ull aa = pack2(av[jj], av[jj]);
                    #pragma unroll
                    for (int ii = 0; ii < 4; ii++) ffma2(c[jj][ii], aa, B[ii]);
                }
            }
        }
        #pragma unroll
        for (int jj = 0; jj < 8; jj++) {
            float2* rowp = (float2*)(G + (size_t)(j0 + ty * 8 + jj) * LD + i0 + tx * 8);
            #pragma unroll
            for (int ii = 0; ii < 4; ii++) {
                float2 v = *(float2*)&c[jj][ii];
                v.x *= TAU_INV; v.y *= TAU_INV;
                rowp[ii] = v;
            }
        }
    }
}

// ---------------- sorted-descending register top-32 insert ----------------
// One pass of max/min: inserts v into sorted T, drops the old minimum.
#define TK_INSERT(T, v)                                   \
    do { float _v = (v);                                  \
        _Pragma("unroll")                                 \
        for (int _k = 0; _k < KTOP; _k++) {               \
            float _t = T[_k];                             \
            T[_k] = fmaxf(_t, _v);                        \
            _v = fminf(_t, _v);                           \
        }                                                 \
    } while (0)

// ---------------- chunked per-row top-32 pass 1 ----------------
__global__ void __launch_bounds__(256) k_topk_chunk() {
    int p = blockIdx.z;
    int c = blockIdx.y;
    int i = blockIdx.x * 256 + threadIdx.x;
    int N = g_N[p];
    if (i >= N) return;

    const float* G = g_G[p];
    int len = (N + NCHUNK - 1) / NCHUNK;
    int j0 = c * len;
    int j1 = j0 + len; if (j1 > N) j1 = N;

    float T[KTOP];
    #pragma unroll
    for (int k = 0; k < KTOP; k++) T[k] = -INFINITY;

    int j = j0;
    for (; j + 4 <= j1; j += 4) {
        float v0 = G[(size_t)(j + 0) * LD + i];
        float v1 = G[(size_t)(j + 1) * LD + i];
        float v2 = G[(size_t)(j + 2) * LD + i];
        float v3 = G[(size_t)(j + 3) * LD + i];
        if (j + 0 != i && v0 > T[KTOP - 1]) TK_INSERT(T, v0);
        if (j + 1 != i && v1 > T[KTOP - 1]) TK_INSERT(T, v1);
        if (j + 2 != i && v2 > T[KTOP - 1]) TK_INSERT(T, v2);
        if (j + 3 != i && v3 > T[KTOP - 1]) TK_INSERT(T, v3);
    }
    for (; j < j1; j++) {
        float v = G[(size_t)j * LD + i];
        if (j != i && v > T[KTOP - 1]) TK_INSERT(T, v);
    }

    float* cand = g_cand[p] + ((size_t)i * NCHUNK + c) * KTOP;
    #pragma unroll
    for (int k = 0; k < KTOP; k++) cand[k] = T[k];
}

// ---------------- merge candidates + logsumexp ----------------
__global__ void __launch_bounds__(256) k_merge() {
    int p = blockIdx.z;
    int i = blockIdx.x * 256 + threadIdx.x;
    int N = g_N[p];
    if (i >= N) return;

    const float4* cand = (const float4*)(g_cand[p] + (size_t)i * NCHUNK * KTOP);
    float T[KTOP];
    #pragma unroll
    for (int k = 0; k < KTOP; k++) T[k] = -INFINITY;

    #pragma unroll 4
    for (int q = 0; q < NCHUNK * KTOP / 4; q++) {
        float4 v = cand[q];
        if (v.x > T[KTOP - 1]) TK_INSERT(T, v.x);
        if (v.y > T[KTOP - 1]) TK_INSERT(T, v.y);
        if (v.z > T[KTOP - 1]) TK_INSERT(T, v.z);
        if (v.w > T[KTOP - 1]) TK_INSERT(T, v.w);
    }

    float pos = g_G[p][(size_t)i * LD + i];
    float m = fmaxf(pos, T[0]);               // T[0] is the max (sorted desc)
    float s = expf(pos - m);
    #pragma unroll
    for (int k = 0; k < KTOP; k++) s += expf(T[k] - m);   // exp(-inf)=0 pads
    g_rowloss[p][i] = m + logf(s) - pos;
}

// ---------------- deterministic reduction ----------------
__global__ void __launch_bounds__(1024) k_reduce() {
    __shared__ float s[1024];
    int p = blockIdx.x;
    int N = g_N[p];
    int t = threadIdx.x;
    float acc = 0.0f;
    for (int i = t; i < N; i += 1024) acc += g_rowloss[p][i];
    s[t] = acc;
    __syncthreads();
    for (int o = 512; o; o >>= 1) {
        if (t < o) s[t] += s[t + o];
        __syncthreads();
    }
    if (t == 0) g_pair[p] = (N >= 4) ? s[0] / (float)N : 0.0f;
}

__global__ void k_final(float* __restrict__ out) {
    out[0] = 0.2f * g_pair[0] + 1.0f * g_pair[1] + 1.0f * g_pair[2];
}

// ---------------- launch ----------------
extern "C" void kernel_launch(void* const* d_in, const int* in_sizes, int n_in,
                              void* d_out, int out_size) {
    const float* ev = (const float*)d_in[0];
    const float* ec = (const float*)d_in[1];
    const float* ep = (const float*)d_in[2];
    const void*  uv = d_in[3]; int nv  = in_sizes[3];
    const void*  uc = d_in[4]; int nc  = in_sizes[4];
    const void*  up = d_in[5]; int np_ = in_sizes[5];

    k_detect<<<1, 64>>>((const int*)uv, nv);
    k_zero<<<8, 512>>>();
    int nmaxb = (nv > nc ? nv : nc);
    if (np_ > nmaxb) nmaxb = np_;
    k_build<<<(nmaxb + 255) / 256, 256>>>(uc, nc, up, np_);
    // pairs: (view->cart), (cart->purchase), (view->purchase)
    k_compact<<<3, 1024>>>(uv, nv, uc, nc, uv, nv);
    k_gather<<<dim3(NMAX / 8, 3), 256>>>(ev, ec, ep);
    k_gemm<<<296, 256>>>();
    k_topk_chunk<<<dim3(NMAX / 256, NCHUNK, 3), 256>>>();
    k_merge<<<dim3(NMAX / 256, 1, 3), 256>>>();
    k_reduce<<<3, 1024>>>();
    k_final<<<1, 1>>>((float*)d_out);
}